// round 11
// baseline (speedup 1.0000x reference)
#include <cuda_runtime.h>

#define NN 100000
#define NE 1000000
#define DD 128
#define NEG 0.01f
#define SCAN_TPB 1024
#define SCAN_EPB (SCAN_TPB * 4)   // 4096 elements per scan block

// Scratch (device globals — no allocation allowed).
// g_cnt invariant: zero at the start of every kernel_launch call.
// (zero at module load; k_agg re-zeros it at the end of each call)
__device__ float  g_el[NN];
__device__ float  g_er[NN];
__device__ int    g_cnt[NN];       // per-dst in-degree
__device__ int    g_off[NN];       // exclusive CSR offsets
__device__ int    g_cur[NN];       // allocation cursors
__device__ float  g_a[NE];         // per-edge exp score (input edge order)
__device__ float2 g_sE[NE];        // CSR-sorted (src_as_float_bits, exp_score)
__device__ int    g_bsum[128];     // scan block sums

// ---- per-node projections: warp per node ----
__global__ void k_proj(const float* __restrict__ h_src,
                       const float* __restrict__ h_dst,
                       const float* __restrict__ attn_l,
                       const float* __restrict__ attn_r,
                       int n_nodes) {
    int gid = blockIdx.x * blockDim.x + threadIdx.x;
    int node = gid >> 5;
    int lane = gid & 31;
    if (node >= n_nodes) return;

    float4 al = ((const float4*)attn_l)[lane];
    float4 ar = ((const float4*)attn_r)[lane];
    float4 hs = ((const float4*)h_src)[(size_t)node * (DD / 4) + lane];
    float4 hd = ((const float4*)h_dst)[(size_t)node * (DD / 4) + lane];

    float vl = hs.x * al.x + hs.y * al.y + hs.z * al.z + hs.w * al.w;
    float vr = hd.x * ar.x + hd.y * ar.y + hd.z * ar.z + hd.w * ar.w;

    #pragma unroll
    for (int o = 16; o > 0; o >>= 1) {
        vl += __shfl_xor_sync(0xffffffffu, vl, o);
        vr += __shfl_xor_sync(0xffffffffu, vr, o);
    }
    if (lane == 0) {
        g_el[node] = vl;
        g_er[node] = vr;
    }
}

// ---- edge pass: score -> leaky_relu -> exp (coalesced), + degree histogram ----
// softmax is shift-invariant; scores ~N(0,~2) so exp without max-shift is safe.
__global__ void k_edge(const int* __restrict__ esrc,
                       const int* __restrict__ edst, int ne) {
    int i = blockIdx.x * blockDim.x + threadIdx.x;
    if (i >= ne) return;
    int s = __ldcs(&esrc[i]);
    int d = __ldcs(&edst[i]);
    float x = g_el[s] + g_er[d];
    float e = x > 0.0f ? x : NEG * x;
    g_a[i] = __expf(e);
    atomicAdd(&g_cnt[d], 1);
}

// ---- scan stage 1: 4 elems/thread, warp-shuffle scan -> exclusive in g_off ----
__global__ void k_scan1(int n_nodes) {
    __shared__ int wsum[SCAN_TPB / 32];
    int t = threadIdx.x;
    int lane = t & 31;
    int warp = t >> 5;
    int g4 = blockIdx.x * SCAN_TPB + t;     // int4 index
    int base = g4 * 4;

    int4 v = make_int4(0, 0, 0, 0);
    if (base < n_nodes) v = ((const int4*)g_cnt)[g4];   // n_nodes % 4 == 0
    int tsum = v.x + v.y + v.z + v.w;

    int x = tsum;
    #pragma unroll
    for (int o = 1; o < 32; o <<= 1) {
        int y = __shfl_up_sync(0xffffffffu, x, o);
        if (lane >= o) x += y;
    }
    if (lane == 31) wsum[warp] = x;
    __syncthreads();

    if (warp == 0) {
        int w = wsum[lane];
        #pragma unroll
        for (int o = 1; o < 32; o <<= 1) {
            int y = __shfl_up_sync(0xffffffffu, w, o);
            if (lane >= o) w += y;
        }
        wsum[lane] = w;
    }
    __syncthreads();

    int wbase = (warp > 0) ? wsum[warp - 1] : 0;
    int excl = wbase + x - tsum;          // exclusive within block
    if (base < n_nodes) {
        int4 o4;
        o4.x = excl;
        o4.y = o4.x + v.x;
        o4.z = o4.y + v.y;
        o4.w = o4.z + v.z;
        ((int4*)g_off)[g4] = o4;
    }
    if (t == SCAN_TPB - 1) g_bsum[blockIdx.x] = wbase + x;  // block total
}

// ---- scan stage 2+3 fused: each block redundantly reduces prior block sums,
//      adds to its offsets, writes g_off and g_cur ----
__global__ void k_scan23(int n_nodes) {
    __shared__ int s_pref;
    int t = threadIdx.x;
    if (t < 32) {
        int v = (t < blockIdx.x) ? g_bsum[t] : 0;   // gridDim <= 32 blocks
        #pragma unroll
        for (int o = 16; o > 0; o >>= 1)
            v += __shfl_xor_sync(0xffffffffu, v, o);
        if (t == 0) s_pref = v;
    }
    __syncthreads();
    int pref = s_pref;

    int g4 = blockIdx.x * SCAN_TPB + t;
    int base = g4 * 4;
    if (base < n_nodes) {
        int4 o4 = ((const int4*)g_off)[g4];
        o4.x += pref; o4.y += pref; o4.z += pref; o4.w += pref;
        ((int4*)g_off)[g4] = o4;
        ((int4*)g_cur)[g4] = o4;
    }
}

// ---- reorder: pure data movement into CSR (coalesced reads, 8B scattered store) ----
__global__ void k_reorder(const int* __restrict__ esrc,
                          const int* __restrict__ edst, int ne) {
    int i = blockIdx.x * blockDim.x + threadIdx.x;
    if (i >= ne) return;
    int d = __ldcs(&edst[i]);
    int s = __ldcs(&esrc[i]);
    float a = __ldcs(&g_a[i]);
    int pos = atomicAdd(&g_cur[d], 1);
    g_sE[pos] = make_float2(__int_as_float(s), a);
}

// ---- aggregation: warp per destination, register acc + in-register softmax sum.
//      Also re-zeros g_cnt for the next launch (keeps the invariant). ----
__global__ void k_agg(const float* __restrict__ h_src,
                      const float* __restrict__ bias,
                      float* __restrict__ out, int n_nodes) {
    int gid = blockIdx.x * blockDim.x + threadIdx.x;
    int d = gid >> 5;
    int lane = gid & 31;
    if (d >= n_nodes) return;

    float4 b4 = ((const float4*)bias)[lane];
    int start = g_off[d];
    int k = g_cnt[d];
    if (lane == 0) g_cnt[d] = 0;     // restore invariant for next launch

    if (k == 0) {
        __stcs(&((float4*)out)[(size_t)d * (DD / 4) + lane], b4);
        return;
    }

    float4 acc = make_float4(0.f, 0.f, 0.f, 0.f);
    float asum = 0.0f;
    int e = start;
    int end = start + k;

    // 2-wide unroll for gather MLP
    for (; e + 1 < end; e += 2) {
        float2 e0 = __ldcs(&g_sE[e]);
        float2 e1 = __ldcs(&g_sE[e + 1]);
        int s0 = __float_as_int(e0.x);
        int s1 = __float_as_int(e1.x);
        float4 h0 = ((const float4*)h_src)[(size_t)s0 * (DD / 4) + lane];
        float4 h1 = ((const float4*)h_src)[(size_t)s1 * (DD / 4) + lane];
        asum += e0.y + e1.y;
        acc.x += e0.y * h0.x + e1.y * h1.x;
        acc.y += e0.y * h0.y + e1.y * h1.y;
        acc.z += e0.y * h0.z + e1.y * h1.z;
        acc.w += e0.y * h0.w + e1.y * h1.w;
    }
    if (e < end) {
        float2 e0 = __ldcs(&g_sE[e]);
        int s0 = __float_as_int(e0.x);
        float4 h0 = ((const float4*)h_src)[(size_t)s0 * (DD / 4) + lane];
        asum += e0.y;
        acc.x += e0.y * h0.x;
        acc.y += e0.y * h0.y;
        acc.z += e0.y * h0.z;
        acc.w += e0.y * h0.w;
    }

    float inv = 1.0f / asum;
    float4 o4;
    o4.x = acc.x * inv + b4.x;
    o4.y = acc.y * inv + b4.y;
    o4.z = acc.z * inv + b4.z;
    o4.w = acc.w * inv + b4.w;
    __stcs(&((float4*)out)[(size_t)d * (DD / 4) + lane], o4);
}

extern "C" void kernel_launch(void* const* d_in, const int* in_sizes, int n_in,
                              void* d_out, int out_size) {
    const float* h_src  = (const float*)d_in[0];
    const float* h_dst  = (const float*)d_in[1];
    const int*   esrc   = (const int*)d_in[2];
    const int*   edst   = (const int*)d_in[3];
    const float* attn_l = (const float*)d_in[4];
    const float* attn_r = (const float*)d_in[5];
    const float* bias   = (const float*)d_in[6];
    float* out = (float*)d_out;

    int n_nodes = in_sizes[0] / DD;
    int ne = in_sizes[2];
    int nbs = (n_nodes + SCAN_EPB - 1) / SCAN_EPB;   // 25 blocks for 100k

    k_proj<<<(n_nodes * 32 + 255) / 256, 256>>>(h_src, h_dst, attn_l, attn_r,
                                                n_nodes);
    k_edge<<<(ne + 255) / 256, 256>>>(esrc, edst, ne);
    k_scan1<<<nbs, SCAN_TPB>>>(n_nodes);
    k_scan23<<<nbs, SCAN_TPB>>>(n_nodes);
    k_reorder<<<(ne + 255) / 256, 256>>>(esrc, edst, ne);
    k_agg<<<(n_nodes * 32 + 255) / 256, 256>>>(h_src, bias, out, n_nodes);
}